// round 4
// baseline (speedup 1.0000x reference)
#include <cuda_runtime.h>
#include <cuda_fp16.h>

#define NN 50000
#define EE 1250000
#define HH 64
#define BB 500
#define BN_EPS 1e-5f

#define NB 2048
#define XLO (-8.0f)
#define INVH 128.0f
#define H_STEP 0.0078125f

// ---------------- device scratch ----------------
__device__ float   g_T[(NB + 1) * HH];      // fp32 raw table (pre-affine, for stats)
__device__ __half2 g_Th[(NB + 1) * 32];     // fp16 table, BN2-affine folded
__device__ __half2 g_embh[100 * 32];        // fp16 edge_emb
__device__ int4    g_srec[EE];              // dst-sorted packed edge records
__device__ int     g_deg[NN];
__device__ int     g_start[NN + 1];
__device__ int     g_cur[NN];
__device__ float   g_hist[5 * NB];
__device__ float   g_h[NN * HH];
__device__ float   g_agg[NN * HH];
__device__ float   g_hg[BB * HH];
__device__ float   g_y1[NN * 64];
__device__ float   g_y2[NN * 32];
__device__ float   g_red[22592];
__device__ float   g_coef[1024];

#define OFF_X   0
#define OFF_D2  64
#define OFF_C1  4160
#define OFF_C2  8256
#define OFF_C3  12352
#define OFF_O1  16448
#define OFF_O2  20544

__device__ __forceinline__ float sp(float x) {
    float t, l;
    asm("ex2.approx.ftz.f32 %0, %1;" : "=f"(t) : "f"(x * 1.44269504f));
    asm("lg2.approx.f32 %0, %1;" : "=f"(l) : "f"(1.0f + t));
    float r = l * 0.69314718f;
    return x > 20.0f ? x : r;
}

// ---------------- setup kernels ----------------

__global__ void kzero() {
    int i = blockIdx.x * 256 + threadIdx.x;
    if (i < 22592) g_red[i] = 0.0f;
    if (i < BB * HH) g_hg[i] = 0.0f;
    if (i < 5 * NB) g_hist[i] = 0.0f;
    if (i < NN) g_deg[i] = 0;
}

__global__ void kcount(const int* __restrict__ ei) {
    int e = blockIdx.x * 256 + threadIdx.x;
    if (e >= EE) return;
    atomicAdd(&g_deg[ei[EE + e]], 1);
}

// single-block prefix scan over 50000 degrees -> starts/cursors
__global__ void kscan() {
    __shared__ int sh[1024];
    const int PER = 49;  // 1024*49 = 50176 >= NN
    int t = threadIdx.x;
    int base = t * PER;
    int s = 0;
    for (int i = 0; i < PER; i++) {
        int n = base + i;
        if (n < NN) s += g_deg[n];
    }
    sh[t] = s;
    __syncthreads();
    for (int o = 1; o < 1024; o <<= 1) {
        int v = (t >= o) ? sh[t - o] : 0;
        __syncthreads();
        sh[t] += v;
        __syncthreads();
    }
    int run = sh[t] - s;  // exclusive prefix of this thread's chunk
    for (int i = 0; i < PER; i++) {
        int n = base + i;
        if (n < NN) {
            g_start[n] = run;
            g_cur[n] = run;
            run += g_deg[n];
        }
    }
    if (t == 1023) g_start[NN] = EE;
}

__global__ void khist(const float* __restrict__ x) {
    __shared__ float hc0[NB], hc1[NB], hs0[NB], hs1[NB], hs2[NB];
    __shared__ float sxs[2];
    int t = threadIdx.x;
    for (int i = t; i < NB; i += 256) { hc0[i] = 0; hc1[i] = 0; hs0[i] = 0; hs1[i] = 0; hs2[i] = 0; }
    if (t < 2) sxs[t] = 0.f;
    __syncthreads();

    float sx = 0.f, sxx = 0.f;
    for (int i = blockIdx.x * 256 + t; i < EE; i += gridDim.x * 256) {
        float v = x[i];
        sx += v; sxx += v * v;
        float u = (v - XLO) * INVH;
        u = fminf(fmaxf(u, 0.0f), (float)NB);
        int b = (int)u; if (b > NB - 1) b = NB - 1;
        float w = u - (float)b;
        float omw = 1.0f - w;
        atomicAdd(&hc0[b], omw);
        atomicAdd(&hc1[b], w);
        atomicAdd(&hs0[b], omw * omw);
        atomicAdd(&hs1[b], w * omw);
        atomicAdd(&hs2[b], w * w);
    }
    atomicAdd(&sxs[0], sx);
    atomicAdd(&sxs[1], sxx);
    __syncthreads();
    for (int i = t; i < NB; i += 256) {
        if (hc0[i] != 0.f) atomicAdd(&g_hist[i], hc0[i]);
        if (hc1[i] != 0.f) atomicAdd(&g_hist[NB + i], hc1[i]);
        if (hs0[i] != 0.f) atomicAdd(&g_hist[2 * NB + i], hs0[i]);
        if (hs1[i] != 0.f) atomicAdd(&g_hist[3 * NB + i], hs1[i]);
        if (hs2[i] != 0.f) atomicAdd(&g_hist[4 * NB + i], hs2[i]);
    }
    if (t == 0) {
        int r = blockIdx.x & 31;
        atomicAdd(&g_red[OFF_X + 2 * r], sxs[0]);
        atomicAdd(&g_red[OFF_X + 2 * r + 1], sxs[1]);
    }
}

__global__ void kfin_d1(const float* __restrict__ w_d1, const float* __restrict__ g_d1,
                        const float* __restrict__ be_d1) {
    __shared__ float S[2];
    if (threadIdx.x == 0) {
        float s = 0.f, q = 0.f;
        for (int r = 0; r < 32; r++) { s += g_red[2 * r]; q += g_red[2 * r + 1]; }
        S[0] = s; S[1] = q;
    }
    __syncthreads();
    float mx = S[0] / (float)EE;
    float vx = S[1] / (float)EE - mx * mx;
    int h = threadIdx.x;
    float w = w_d1[h];
    float a = w * rsqrtf(vx * w * w + BN_EPS) * g_d1[h];
    g_coef[h] = a;
    g_coef[64 + h] = -mx * a + be_d1[h];
}

__global__ void ktable(const float* __restrict__ w_d2) {
    __shared__ float spv[64];
    int b = blockIdx.x, k = threadIdx.x;
    float xb = XLO + (float)b * H_STEP;
    spv[k] = sp(g_coef[k] * xb + g_coef[64 + k]);
    __syncthreads();
    float acc = 0.f;
#pragma unroll 8
    for (int f = 0; f < 64; f++) acc += spv[f] * __ldg(&w_d2[k * 64 + f]);
    g_T[b * 64 + k] = acc;
}

__global__ void kd2stat() {
    int k = threadIdx.x;
    int b0 = blockIdx.x * 128;
    float s = 0.f, q = 0.f;
    float tp = g_T[b0 * 64 + k];
    for (int j = 0; j < 128; j++) {
        int b = b0 + j;
        float tn = g_T[(b + 1) * 64 + k];
        float c0 = g_hist[b], c1 = g_hist[NB + b];
        float s0 = g_hist[2 * NB + b], s1 = g_hist[3 * NB + b], s2v = g_hist[4 * NB + b];
        s += c0 * tp + c1 * tn;
        q += s0 * tp * tp + 2.0f * s1 * tp * tn + s2v * tn * tn;
        tp = tn;
    }
    int r = blockIdx.x & 31;
    atomicAdd(&g_red[OFF_D2 + r * 128 + k], s);
    atomicAdd(&g_red[OFF_D2 + r * 128 + 64 + k], q);
}

__global__ void kfinbn(int redoff, int F, float cnt, const float* __restrict__ g,
                       const float* __restrict__ be, int coefoff) {
    int k = threadIdx.x;
    if (k >= F) return;
    float s = 0.f, q = 0.f;
    for (int r = 0; r < 32; r++) {
        s += g_red[redoff + r * 2 * F + k];
        q += g_red[redoff + r * 2 * F + F + k];
    }
    float m = s / cnt;
    float v = q / cnt - m * m;
    float sc = g[k] * rsqrtf(v + BN_EPS);
    g_coef[coefoff + k] = sc;
    g_coef[coefoff + 64 + k] = be[k] - m * sc;
}

__global__ void ktaffine() {
    int i = blockIdx.x * 256 + threadIdx.x;
    if (i >= (NB + 1) * 32) return;
    int b = i >> 5;
    int k2 = (i & 31) * 2;
    float v0 = g_T[b * 64 + k2]     * g_coef[128 + k2]     + g_coef[192 + k2];
    float v1 = g_T[b * 64 + k2 + 1] * g_coef[128 + k2 + 1] + g_coef[192 + k2 + 1];
    g_Th[i] = __floats2half2_rn(v0, v1);
}

__global__ void kembh(const float* __restrict__ edge_emb) {
    int i = blockIdx.x * 256 + threadIdx.x;
    if (i >= 100 * 32) return;
    g_embh[i] = __floats2half2_rn(edge_emb[2 * i], edge_emb[2 * i + 1]);
}

// scatter packed records into dst-sorted CSR order
__global__ void kscatter(const int* __restrict__ ei, const int* __restrict__ et,
                         const float* __restrict__ x) {
    int e = blockIdx.x * 256 + threadIdx.x;
    if (e >= EE) return;
    int dst = ei[EE + e];
    int pos = atomicAdd(&g_cur[dst], 1);
    float xv = x[e];
    float u = (xv - XLO) * INVH;
    u = fminf(fmaxf(u, 0.0f), (float)NB);
    int b = (int)u; if (b > NB - 1) b = NB - 1;
    float w = u - (float)b;
    g_srec[pos] = make_int4(ei[e], et[e] | (b << 7), __float_as_int(w), 0);
}

__global__ void kinith(const int* __restrict__ node_type, const float* __restrict__ node_emb) {
    int i = blockIdx.x * 256 + threadIdx.x;
    int n = i >> 6, k = i & 63;
    g_h[i] = node_emb[node_type[n] * 64 + k];
}

// ---------------- gconv: CSR gather, 8 threads/node, no atomics ----------------
__global__ void kedge() {
    int idx = blockIdx.x * 256 + threadIdx.x;
    int node = idx >> 3;
    if (node >= NN) return;
    int lane8 = idx & 7;
    int p0 = g_start[node];
    int p1 = g_start[node + 1];
    int fo2 = lane8 * 4;
    int f0 = lane8 * 8;

    float a0 = 0.f, a1 = 0.f, a2 = 0.f, a3 = 0.f;
    float a4 = 0.f, a5 = 0.f, a6 = 0.f, a7 = 0.f;

#pragma unroll 2
    for (int p = p0; p < p1; p++) {
        int4 rec = __ldg(&g_srec[p]);
        int src = rec.x;
        int ty = rec.y & 127;
        int b = rec.y >> 7;
        float w = __int_as_float(rec.z);

        float4 tr0 = __ldg((const float4*)&g_Th[b * 32 + fo2]);
        float4 tr1 = __ldg((const float4*)&g_Th[(b + 1) * 32 + fo2]);
        float4 emr = __ldg((const float4*)&g_embh[ty * 32 + fo2]);
        float4 hs0 = *(const float4*)&g_h[src * 64 + f0];
        float4 hs1 = *(const float4*)&g_h[src * 64 + f0 + 4];

        const __half2* t0h = (const __half2*)&tr0;
        const __half2* t1h = (const __half2*)&tr1;
        const __half2* emh = (const __half2*)&emr;

        float m[8];
#pragma unroll
        for (int j = 0; j < 4; j++) {
            float2 aa = __half22float2(t0h[j]);
            float2 cc = __half22float2(t1h[j]);
            float2 em = __half22float2(emh[j]);
            m[2 * j]     = fmaf(w, cc.x - aa.x, aa.x) * em.x;
            m[2 * j + 1] = fmaf(w, cc.y - aa.y, aa.y) * em.y;
        }
        a0 += sp(hs0.x + m[0]);
        a1 += sp(hs0.y + m[1]);
        a2 += sp(hs0.z + m[2]);
        a3 += sp(hs0.w + m[3]);
        a4 += sp(hs1.x + m[4]);
        a5 += sp(hs1.y + m[5]);
        a6 += sp(hs1.z + m[6]);
        a7 += sp(hs1.w + m[7]);
    }

    float4 hn0 = *(const float4*)&g_h[node * 64 + f0];
    float4 hn1 = *(const float4*)&g_h[node * 64 + f0 + 4];
    float4 o0 = make_float4(a0 + hn0.x, a1 + hn0.y, a2 + hn0.z, a3 + hn0.w);
    float4 o1 = make_float4(a4 + hn1.x, a5 + hn1.y, a6 + hn1.z, a7 + hn1.w);
    *(float4*)&g_agg[node * 64 + f0] = o0;
    *(float4*)&g_agg[node * 64 + f0 + 4] = o1;
}

__global__ void knstat(int redoff) {
    int t = threadIdx.x;
    int f0 = (t & 15) * 4;
    float4 s = {0, 0, 0, 0}, q = {0, 0, 0, 0};
    for (int n = blockIdx.x * 16 + (t >> 4); n < NN; n += gridDim.x * 16) {
        float4 v = *(const float4*)&g_agg[n * 64 + f0];
        s.x += v.x; s.y += v.y; s.z += v.z; s.w += v.w;
        q.x += v.x * v.x; q.y += v.y * v.y; q.z += v.z * v.z; q.w += v.w * v.w;
    }
    __shared__ float ssum[64], ssq[64];
    if (t < 64) { ssum[t] = 0.f; ssq[t] = 0.f; }
    __syncthreads();
    atomicAdd(&ssum[f0 + 0], s.x); atomicAdd(&ssum[f0 + 1], s.y);
    atomicAdd(&ssum[f0 + 2], s.z); atomicAdd(&ssum[f0 + 3], s.w);
    atomicAdd(&ssq[f0 + 0], q.x); atomicAdd(&ssq[f0 + 1], q.y);
    atomicAdd(&ssq[f0 + 2], q.z); atomicAdd(&ssq[f0 + 3], q.w);
    __syncthreads();
    if (t < 64) {
        int r = blockIdx.x & 31;
        atomicAdd(&g_red[redoff + r * 128 + t], ssum[t]);
        atomicAdd(&g_red[redoff + r * 128 + 64 + t], ssq[t]);
    }
}

__global__ void kapply(int coefoff, int doact, int dohg, const int* __restrict__ batch) {
    int i = blockIdx.x * 256 + threadIdx.x;
    int n = i >> 4;
    int f0 = (i & 15) * 4;
    float4 v  = *(const float4*)&g_agg[n * 64 + f0];
    float4 sc = *(const float4*)&g_coef[coefoff + f0];
    float4 sh = *(const float4*)&g_coef[coefoff + 64 + f0];
    v.x = v.x * sc.x + sh.x; v.y = v.y * sc.y + sh.y;
    v.z = v.z * sc.z + sh.z; v.w = v.w * sc.w + sh.w;
    if (doact) { v.x = sp(v.x); v.y = sp(v.y); v.z = sp(v.z); v.w = sp(v.w); }
    *(float4*)&g_h[n * 64 + f0] = v;
    if (dohg) {
        int b = batch[n];
        float* o = &g_hg[b * 64 + f0];
        asm volatile("red.global.add.v4.f32 [%0], {%1, %2, %3, %4};"
                     :: "l"(o), "f"(v.x), "f"(v.y), "f"(v.z), "f"(v.w) : "memory");
    }
}

__global__ void kstage1(const int* __restrict__ batch, const float* __restrict__ w_o1,
                        const float* __restrict__ b_o1) {
    __shared__ float snf[4][128];
    __shared__ float ssum[64], ssq[64];
    int t = threadIdx.x, q = t >> 6, k = t & 63;
    int n = blockIdx.x * 4 + q;
    snf[q][k]      = g_h[n * 64 + k];
    snf[q][64 + k] = g_hg[batch[n] * 64 + k];
    if (t < 64) { ssum[t] = 0.f; ssq[t] = 0.f; }
    __syncthreads();
    float acc = b_o1[k];
#pragma unroll
    for (int j4 = 0; j4 < 32; j4++) {
        float4 w4 = __ldg((const float4*)&w_o1[k * 128 + j4 * 4]);
        float4 v = *(const float4*)&snf[q][j4 * 4];
        acc += v.x * w4.x + v.y * w4.y + v.z * w4.z + v.w * w4.w;
    }
    g_y1[n * 64 + k] = acc;
    atomicAdd(&ssum[k], acc);
    atomicAdd(&ssq[k], acc * acc);
    __syncthreads();
    if (t < 64) {
        int r = blockIdx.x & 31;
        atomicAdd(&g_red[OFF_O1 + r * 128 + t], ssum[t]);
        atomicAdd(&g_red[OFF_O1 + r * 128 + 64 + t], ssq[t]);
    }
}

__global__ void kstage2(const float* __restrict__ w_o2, const float* __restrict__ b_o2) {
    __shared__ float sv[4][64];
    __shared__ float ssum[32], ssq[32];
    int t = threadIdx.x, q = t >> 5, k = t & 31;
    int n = blockIdx.x * 4 + q;
    {
        float a = g_y1[n * 64 + k]      * g_coef[640 + k]      + g_coef[704 + k];
        float b = g_y1[n * 64 + 32 + k] * g_coef[640 + 32 + k] + g_coef[704 + 32 + k];
        sv[q][k] = sp(a);
        sv[q][32 + k] = sp(b);
    }
    if (t < 32) { ssum[t] = 0.f; ssq[t] = 0.f; }
    __syncthreads();
    float acc = b_o2[k];
#pragma unroll
    for (int j4 = 0; j4 < 16; j4++) {
        float4 w4 = __ldg((const float4*)&w_o2[k * 64 + j4 * 4]);
        float4 v = *(const float4*)&sv[q][j4 * 4];
        acc += v.x * w4.x + v.y * w4.y + v.z * w4.z + v.w * w4.w;
    }
    g_y2[n * 32 + k] = acc;
    atomicAdd(&ssum[k], acc);
    atomicAdd(&ssq[k], acc * acc);
    __syncthreads();
    if (t < 32) {
        int r = blockIdx.x & 31;
        atomicAdd(&g_red[OFF_O2 + r * 64 + t], ssum[t]);
        atomicAdd(&g_red[OFF_O2 + r * 64 + 32 + t], ssq[t]);
    }
}

__global__ void kstage3(const float* __restrict__ w_o3, const float* __restrict__ b_o3,
                        float* __restrict__ out) {
    __shared__ float sv[2][32];
    int t = threadIdx.x;
    int n2 = blockIdx.x * 2;
    if (t < 64) {
        int q = t >> 5, k = t & 31;
        float a = g_y2[(n2 + q) * 32 + k] * g_coef[768 + k] + g_coef[832 + k];
        sv[q][k] = sp(a);
    }
    __syncthreads();
    int q = t >> 7, c = t & 127;
    int n = n2 + q;
    float acc = b_o3[c];
#pragma unroll
    for (int j4 = 0; j4 < 8; j4++) {
        float4 w4 = __ldg((const float4*)&w_o3[c * 32 + j4 * 4]);
        float4 v = *(const float4*)&sv[q][j4 * 4];
        acc += v.x * w4.x + v.y * w4.y + v.z * w4.z + v.w * w4.w;
    }
    if (c < 64) out[(long)n * 64 + c] = acc;
    else        out[(long)NN * 64 + (long)n * 64 + (c - 64)] = acc;
}

// ---------------- launch ----------------
extern "C" void kernel_launch(void* const* d_in, const int* in_sizes, int n_in,
                              void* d_out, int out_size) {
    const float* x         = (const float*)d_in[0];
    const int*   node_type = (const int*)d_in[1];
    const int*   edge_type = (const int*)d_in[2];
    const int*   edge_index= (const int*)d_in[3];
    const int*   batch     = (const int*)d_in[4];
    const float* node_emb  = (const float*)d_in[5];
    const float* edge_emb  = (const float*)d_in[6];
    const float* w_d1      = (const float*)d_in[7];
    const float* g_d1      = (const float*)d_in[9];
    const float* be_d1     = (const float*)d_in[10];
    const float* w_d2      = (const float*)d_in[11];
    const float* g_d2      = (const float*)d_in[13];
    const float* be_d2     = (const float*)d_in[14];
    const float* g_c1      = (const float*)d_in[15];
    const float* be_c1     = (const float*)d_in[16];
    const float* g_c2      = (const float*)d_in[17];
    const float* be_c2     = (const float*)d_in[18];
    const float* g_c3      = (const float*)d_in[19];
    const float* be_c3     = (const float*)d_in[20];
    const float* w_o1      = (const float*)d_in[21];
    const float* b_o1      = (const float*)d_in[22];
    const float* g_o1      = (const float*)d_in[23];
    const float* be_o1     = (const float*)d_in[24];
    const float* w_o2      = (const float*)d_in[25];
    const float* b_o2      = (const float*)d_in[26];
    const float* g_o2      = (const float*)d_in[27];
    const float* be_o2     = (const float*)d_in[28];
    const float* w_o3      = (const float*)d_in[29];
    const float* b_o3      = (const float*)d_in[30];

    kzero<<<196, 256>>>();
    kcount<<<(EE + 255) / 256, 256>>>(edge_index);
    kscan<<<1, 1024>>>();
    khist<<<256, 256>>>(x);                      // launch idx 3 -> profiled
    kfin_d1<<<1, 64>>>(w_d1, g_d1, be_d1);
    ktable<<<NB + 1, 64>>>(w_d2);
    kd2stat<<<16, 64>>>();
    kfinbn<<<1, 64>>>(OFF_D2, 64, (float)EE, g_d2, be_d2, 128);
    ktaffine<<<((NB + 1) * 32 + 255) / 256, 256>>>();
    kembh<<<13, 256>>>(edge_emb);
    kscatter<<<(EE + 255) / 256, 256>>>(edge_index, edge_type, x);
    kinith<<<12500, 256>>>(node_type, node_emb);

    const int   statoff[3] = {OFF_C1, OFF_C2, OFF_C3};
    const int   coefoff[3] = {256, 384, 512};
    const float* gs[3]  = {g_c1, g_c2, g_c3};
    const float* bes[3] = {be_c1, be_c2, be_c3};
    for (int l = 0; l < 3; l++) {
        kedge<<<(NN * 8 + 255) / 256, 256>>>();
        knstat<<<256, 256>>>(statoff[l]);
        kfinbn<<<1, 64>>>(statoff[l], 64, (float)NN, gs[l], bes[l], coefoff[l]);
        kapply<<<3125, 256>>>(coefoff[l], (l < 2) ? 1 : 0, (l == 2) ? 1 : 0, batch);
    }

    kstage1<<<12500, 256>>>(batch, w_o1, b_o1);
    kfinbn<<<1, 64>>>(OFF_O1, 64, (float)NN, g_o1, be_o1, 640);
    kstage2<<<12500, 128>>>(w_o2, b_o2);
    kfinbn<<<1, 64>>>(OFF_O2, 32, (float)NN, g_o2, be_o2, 768);
    kstage3<<<25000, 256>>>(w_o3, b_o3, (float*)d_out);
}

// round 5
// speedup vs baseline: 1.5186x; 1.5186x over previous
#include <cuda_runtime.h>

#define NN 50000
#define EE 1250000
#define HH 64
#define BB 500
#define BN_EPS 1e-5f

#define NB 2048
#define XLO (-8.0f)
#define INVH 128.0f
#define H_STEP 0.0078125f

// ---------------- device scratch ----------------
__device__ float   g_T[(NB + 1) * HH];      // fp32 table; BN2 affine folded in-place later
__device__ int4    g_srec[EE];              // dst-sorted records: src, dst, ty|bin<<7, w
__device__ int     g_deg[NN];
__device__ int     g_pref[NN];
__device__ int     g_bsum[256];
__device__ int     g_boff[256];
__device__ int     g_cur[NN];
__device__ float   g_hist[3 * NB];          // n, sum(w), sum(w^2)
__device__ float   g_h[NN * HH];
__device__ float   g_agg[NN * HH];
__device__ float   g_hg[BB * HH];
__device__ float   g_y1[NN * 64];
__device__ float   g_y2[NN * 32];
__device__ float   g_red[22592];
__device__ float   g_coef[1024];

#define OFF_X   0
#define OFF_D2  64
#define OFF_C1  4160
#define OFF_C2  8256
#define OFF_C3  12352
#define OFF_O1  16448
#define OFF_O2  20544

__device__ __forceinline__ float sp(float x) {
    float t, l;
    asm("ex2.approx.ftz.f32 %0, %1;" : "=f"(t) : "f"(x * 1.44269504f));
    asm("lg2.approx.f32 %0, %1;" : "=f"(l) : "f"(1.0f + t));
    float r = l * 0.69314718f;
    return x > 20.0f ? x : r;
}

// ---------------- setup kernels ----------------

__global__ void kzero() {
    int i = blockIdx.x * 256 + threadIdx.x;
    if (i < 22592) g_red[i] = 0.0f;
    if (i < BB * HH) g_hg[i] = 0.0f;
    if (i < 3 * NB) g_hist[i] = 0.0f;
    if (i < NN) g_deg[i] = 0;
}

__global__ void kcount(const int* __restrict__ ei) {
    int e = blockIdx.x * 256 + threadIdx.x;
    if (e >= EE) return;
    atomicAdd(&g_deg[ei[EE + e]], 1);
}

__global__ void kscan1() {
    __shared__ int sh[256];
    int t = threadIdx.x;
    int i = blockIdx.x * 256 + t;
    int v = (i < NN) ? g_deg[i] : 0;
    sh[t] = v;
    __syncthreads();
    for (int o = 1; o < 256; o <<= 1) {
        int u = (t >= o) ? sh[t - o] : 0;
        __syncthreads();
        sh[t] += u;
        __syncthreads();
    }
    if (i < NN) g_pref[i] = sh[t];
    if (t == 255) g_bsum[blockIdx.x] = sh[255];
}

__global__ void kscan2() {
    __shared__ int sh[256];
    int t = threadIdx.x;
    int v = (t < 196) ? g_bsum[t] : 0;
    sh[t] = v;
    __syncthreads();
    for (int o = 1; o < 256; o <<= 1) {
        int u = (t >= o) ? sh[t - o] : 0;
        __syncthreads();
        sh[t] += u;
        __syncthreads();
    }
    g_boff[t] = sh[t] - v;
}

__global__ void kscan3() {
    int i = blockIdx.x * 256 + threadIdx.x;
    if (i < NN) g_cur[i] = g_pref[i] - g_deg[i] + g_boff[blockIdx.x];
}

__global__ void khist(const float* __restrict__ x) {
    __shared__ float hn[NB], hw[NB], hw2[NB];
    __shared__ float sxs[2];
    int t = threadIdx.x;
    for (int i = t; i < NB; i += 256) { hn[i] = 0; hw[i] = 0; hw2[i] = 0; }
    if (t < 2) sxs[t] = 0.f;
    __syncthreads();

    float sx = 0.f, sxx = 0.f;
    for (int i = blockIdx.x * 256 + t; i < EE; i += gridDim.x * 256) {
        float v = x[i];
        sx += v; sxx += v * v;
        float u = (v - XLO) * INVH;
        u = fminf(fmaxf(u, 0.0f), (float)NB);
        int b = (int)u; if (b > NB - 1) b = NB - 1;
        float w = u - (float)b;
        atomicAdd(&hn[b], 1.0f);
        atomicAdd(&hw[b], w);
        atomicAdd(&hw2[b], w * w);
    }
    atomicAdd(&sxs[0], sx);
    atomicAdd(&sxs[1], sxx);
    __syncthreads();
    for (int i = t * 4; i < NB; i += 1024) {
        float4 a = *(const float4*)&hn[i];
        float4 b = *(const float4*)&hw[i];
        float4 c = *(const float4*)&hw2[i];
        asm volatile("red.global.add.v4.f32 [%0], {%1, %2, %3, %4};"
                     :: "l"(&g_hist[i]), "f"(a.x), "f"(a.y), "f"(a.z), "f"(a.w) : "memory");
        asm volatile("red.global.add.v4.f32 [%0], {%1, %2, %3, %4};"
                     :: "l"(&g_hist[NB + i]), "f"(b.x), "f"(b.y), "f"(b.z), "f"(b.w) : "memory");
        asm volatile("red.global.add.v4.f32 [%0], {%1, %2, %3, %4};"
                     :: "l"(&g_hist[2 * NB + i]), "f"(c.x), "f"(c.y), "f"(c.z), "f"(c.w) : "memory");
    }
    if (t == 0) {
        int r = blockIdx.x & 31;
        atomicAdd(&g_red[OFF_X + 2 * r], sxs[0]);
        atomicAdd(&g_red[OFF_X + 2 * r + 1], sxs[1]);
    }
}

__global__ void kfin_d1(const float* __restrict__ w_d1, const float* __restrict__ g_d1,
                        const float* __restrict__ be_d1) {
    __shared__ float S[2];
    if (threadIdx.x == 0) {
        float s = 0.f, q = 0.f;
        for (int r = 0; r < 32; r++) { s += g_red[2 * r]; q += g_red[2 * r + 1]; }
        S[0] = s; S[1] = q;
    }
    __syncthreads();
    float mx = S[0] / (float)EE;
    float vx = S[1] / (float)EE - mx * mx;
    int h = threadIdx.x;
    float w = w_d1[h];
    float a = w * rsqrtf(vx * w * w + BN_EPS) * g_d1[h];
    g_coef[h] = a;
    g_coef[64 + h] = -mx * a + be_d1[h];
}

__global__ void ktable(const float* __restrict__ w_d2) {
    __shared__ float spv[64];
    int b = blockIdx.x, k = threadIdx.x;
    float xb = XLO + (float)b * H_STEP;
    spv[k] = sp(g_coef[k] * xb + g_coef[64 + k]);
    __syncthreads();
    float acc = 0.f;
#pragma unroll 8
    for (int f = 0; f < 64; f++) acc += spv[f] * __ldg(&w_d2[k * 64 + f]);
    g_T[b * 64 + k] = acc;
}

__global__ void kd2stat() {
    int k = threadIdx.x;
    int b0 = blockIdx.x * 128;
    float s = 0.f, q = 0.f;
    float tp = g_T[b0 * 64 + k];
    for (int j = 0; j < 128; j++) {
        int b = b0 + j;
        float tn = g_T[(b + 1) * 64 + k];
        float n  = g_hist[b];
        float c1 = g_hist[NB + b];
        float s2 = g_hist[2 * NB + b];
        float c0 = n - c1;
        float s1 = c1 - s2;
        float s0 = n - 2.0f * c1 + s2;
        s += c0 * tp + c1 * tn;
        q += s0 * tp * tp + 2.0f * s1 * tp * tn + s2 * tn * tn;
        tp = tn;
    }
    int r = blockIdx.x & 31;
    atomicAdd(&g_red[OFF_D2 + r * 128 + k], s);
    atomicAdd(&g_red[OFF_D2 + r * 128 + 64 + k], q);
}

__global__ void kfinbn(int redoff, int F, float cnt, const float* __restrict__ g,
                       const float* __restrict__ be, int coefoff) {
    int k = threadIdx.x;
    if (k >= F) return;
    float s = 0.f, q = 0.f;
    for (int r = 0; r < 32; r++) {
        s += g_red[redoff + r * 2 * F + k];
        q += g_red[redoff + r * 2 * F + F + k];
    }
    float m = s / cnt;
    float v = q / cnt - m * m;
    float sc = g[k] * rsqrtf(v + BN_EPS);
    g_coef[coefoff + k] = sc;
    g_coef[coefoff + 64 + k] = be[k] - m * sc;
}

// fold BN2 affine into fp32 table (in place)
__global__ void ktaffine() {
    int i = blockIdx.x * 256 + threadIdx.x;
    if (i >= (NB + 1) * 64) return;
    int k = i & 63;
    g_T[i] = g_T[i] * g_coef[128 + k] + g_coef[192 + k];
}

// scatter packed records into dst-sorted order
__global__ void kscatter(const int* __restrict__ ei, const int* __restrict__ et,
                         const float* __restrict__ x) {
    int e = blockIdx.x * 256 + threadIdx.x;
    if (e >= EE) return;
    int dst = ei[EE + e];
    int pos = atomicAdd(&g_cur[dst], 1);
    float xv = x[e];
    float u = (xv - XLO) * INVH;
    u = fminf(fmaxf(u, 0.0f), (float)NB);
    int b = (int)u; if (b > NB - 1) b = NB - 1;
    float w = u - (float)b;
    g_srec[pos] = make_int4(ei[e], dst, et[e] | (b << 7), __float_as_int(w));
}

__global__ void kinith(const int* __restrict__ node_type, const float* __restrict__ node_emb) {
    int i = blockIdx.x * 256 + threadIdx.x;
    int n = i >> 6, k = i & 63;
    float v = node_emb[node_type[n] * 64 + k];
    g_h[i] = v;
    g_agg[i] = v;
}

// ---------------- gconv: per-edge, 8 thr/edge, warp dst-combine ----------------
__global__ void kedge(const float* __restrict__ edge_emb) {
    int idx = blockIdx.x * 256 + threadIdx.x;
    int e = idx >> 3;
    int lane = threadIdx.x & 31;
    int lane8 = idx & 7;
    bool act = (e < EE);
    int4 rec = act ? __ldg(&g_srec[e]) : make_int4(0, -1 - lane, 0, 0);
    int src = rec.x, dst = rec.y;
    int ty = rec.z & 127, b = rec.z >> 7;
    float w = __int_as_float(rec.w);
    int f0 = lane8 * 8;

    float m[8];
#pragma unroll
    for (int j = 0; j < 8; j++) m[j] = 0.f;

    if (act) {
        float4 t0a = *(const float4*)&g_T[b * 64 + f0];
        float4 t0b = *(const float4*)&g_T[b * 64 + f0 + 4];
        float4 t1a = *(const float4*)&g_T[(b + 1) * 64 + f0];
        float4 t1b = *(const float4*)&g_T[(b + 1) * 64 + f0 + 4];
        float4 ea  = __ldg((const float4*)&edge_emb[ty * 64 + f0]);
        float4 eb  = __ldg((const float4*)&edge_emb[ty * 64 + f0 + 4]);
        float4 ha  = *(const float4*)&g_h[src * 64 + f0];
        float4 hb  = *(const float4*)&g_h[src * 64 + f0 + 4];
        m[0] = sp(ha.x + fmaf(w, t1a.x - t0a.x, t0a.x) * ea.x);
        m[1] = sp(ha.y + fmaf(w, t1a.y - t0a.y, t0a.y) * ea.y);
        m[2] = sp(ha.z + fmaf(w, t1a.z - t0a.z, t0a.z) * ea.z);
        m[3] = sp(ha.w + fmaf(w, t1a.w - t0a.w, t0a.w) * ea.w);
        m[4] = sp(hb.x + fmaf(w, t1b.x - t0b.x, t0b.x) * eb.x);
        m[5] = sp(hb.y + fmaf(w, t1b.y - t0b.y, t0b.y) * eb.y);
        m[6] = sp(hb.z + fmaf(w, t1b.z - t0b.z, t0b.z) * eb.z);
        m[7] = sp(hb.w + fmaf(w, t1b.w - t0b.w, t0b.w) * eb.w);
    }

    // warp-level combine of same-dst edges (sorted -> usually all 4 match)
#pragma unroll
    for (int k = 8; k <= 16; k <<= 1) {
        int pd = __shfl_xor_sync(0xffffffffu, dst, k);
        int pa = __shfl_xor_sync(0xffffffffu, (int)act, k);
        float pm[8];
#pragma unroll
        for (int j = 0; j < 8; j++) pm[j] = __shfl_xor_sync(0xffffffffu, m[j], k);
        bool take = act && pa && (pd == dst);
        if (take) {
#pragma unroll
            for (int j = 0; j < 8; j++) m[j] += pm[j];
            if (lane & k) act = false;
        }
    }

    if (act) {
        float* o = &g_agg[dst * 64 + f0];
        asm volatile("red.global.add.v4.f32 [%0], {%1, %2, %3, %4};"
                     :: "l"(o), "f"(m[0]), "f"(m[1]), "f"(m[2]), "f"(m[3]) : "memory");
        asm volatile("red.global.add.v4.f32 [%0], {%1, %2, %3, %4};"
                     :: "l"(o + 4), "f"(m[4]), "f"(m[5]), "f"(m[6]), "f"(m[7]) : "memory");
    }
}

__global__ void knstat(int redoff) {
    int t = threadIdx.x;
    int f0 = (t & 15) * 4;
    float4 s = {0, 0, 0, 0}, q = {0, 0, 0, 0};
    for (int n = blockIdx.x * 16 + (t >> 4); n < NN; n += gridDim.x * 16) {
        float4 v = *(const float4*)&g_agg[n * 64 + f0];
        s.x += v.x; s.y += v.y; s.z += v.z; s.w += v.w;
        q.x += v.x * v.x; q.y += v.y * v.y; q.z += v.z * v.z; q.w += v.w * v.w;
    }
    __shared__ float ssum[64], ssq[64];
    if (t < 64) { ssum[t] = 0.f; ssq[t] = 0.f; }
    __syncthreads();
    atomicAdd(&ssum[f0 + 0], s.x); atomicAdd(&ssum[f0 + 1], s.y);
    atomicAdd(&ssum[f0 + 2], s.z); atomicAdd(&ssum[f0 + 3], s.w);
    atomicAdd(&ssq[f0 + 0], q.x); atomicAdd(&ssq[f0 + 1], q.y);
    atomicAdd(&ssq[f0 + 2], q.z); atomicAdd(&ssq[f0 + 3], q.w);
    __syncthreads();
    if (t < 64) {
        int r = blockIdx.x & 31;
        atomicAdd(&g_red[redoff + r * 128 + t], ssum[t]);
        atomicAdd(&g_red[redoff + r * 128 + 64 + t], ssq[t]);
    }
}

__global__ void kapply(int coefoff, int doact, int dohg, const int* __restrict__ batch) {
    int i = blockIdx.x * 256 + threadIdx.x;
    int n = i >> 4;
    int f0 = (i & 15) * 4;
    float4 v  = *(const float4*)&g_agg[n * 64 + f0];
    float4 sc = *(const float4*)&g_coef[coefoff + f0];
    float4 sh = *(const float4*)&g_coef[coefoff + 64 + f0];
    v.x = v.x * sc.x + sh.x; v.y = v.y * sc.y + sh.y;
    v.z = v.z * sc.z + sh.z; v.w = v.w * sc.w + sh.w;
    if (doact) { v.x = sp(v.x); v.y = sp(v.y); v.z = sp(v.z); v.w = sp(v.w); }
    *(float4*)&g_h[n * 64 + f0] = v;
    *(float4*)&g_agg[n * 64 + f0] = v;   // re-init accumulator for next layer
    if (dohg) {
        int b = batch[n];
        float* o = &g_hg[b * 64 + f0];
        asm volatile("red.global.add.v4.f32 [%0], {%1, %2, %3, %4};"
                     :: "l"(o), "f"(v.x), "f"(v.y), "f"(v.z), "f"(v.w) : "memory");
    }
}

__global__ void kstage1(const int* __restrict__ batch, const float* __restrict__ w_o1,
                        const float* __restrict__ b_o1) {
    __shared__ float snf[4][128];
    __shared__ float ssum[64], ssq[64];
    int t = threadIdx.x, q = t >> 6, k = t & 63;
    int n = blockIdx.x * 4 + q;
    snf[q][k]      = g_h[n * 64 + k];
    snf[q][64 + k] = g_hg[batch[n] * 64 + k];
    if (t < 64) { ssum[t] = 0.f; ssq[t] = 0.f; }
    __syncthreads();
    float acc = b_o1[k];
#pragma unroll
    for (int j4 = 0; j4 < 32; j4++) {
        float4 w4 = __ldg((const float4*)&w_o1[k * 128 + j4 * 4]);
        float4 v = *(const float4*)&snf[q][j4 * 4];
        acc += v.x * w4.x + v.y * w4.y + v.z * w4.z + v.w * w4.w;
    }
    g_y1[n * 64 + k] = acc;
    atomicAdd(&ssum[k], acc);
    atomicAdd(&ssq[k], acc * acc);
    __syncthreads();
    if (t < 64) {
        int r = blockIdx.x & 31;
        atomicAdd(&g_red[OFF_O1 + r * 128 + t], ssum[t]);
        atomicAdd(&g_red[OFF_O1 + r * 128 + 64 + t], ssq[t]);
    }
}

__global__ void kstage2(const float* __restrict__ w_o2, const float* __restrict__ b_o2) {
    __shared__ float sv[4][64];
    __shared__ float ssum[32], ssq[32];
    int t = threadIdx.x, q = t >> 5, k = t & 31;
    int n = blockIdx.x * 4 + q;
    {
        float a = g_y1[n * 64 + k]      * g_coef[640 + k]      + g_coef[704 + k];
        float b = g_y1[n * 64 + 32 + k] * g_coef[640 + 32 + k] + g_coef[704 + 32 + k];
        sv[q][k] = sp(a);
        sv[q][32 + k] = sp(b);
    }
    if (t < 32) { ssum[t] = 0.f; ssq[t] = 0.f; }
    __syncthreads();
    float acc = b_o2[k];
#pragma unroll
    for (int j4 = 0; j4 < 16; j4++) {
        float4 w4 = __ldg((const float4*)&w_o2[k * 64 + j4 * 4]);
        float4 v = *(const float4*)&sv[q][j4 * 4];
        acc += v.x * w4.x + v.y * w4.y + v.z * w4.z + v.w * w4.w;
    }
    g_y2[n * 32 + k] = acc;
    atomicAdd(&ssum[k], acc);
    atomicAdd(&ssq[k], acc * acc);
    __syncthreads();
    if (t < 32) {
        int r = blockIdx.x & 31;
        atomicAdd(&g_red[OFF_O2 + r * 64 + t], ssum[t]);
        atomicAdd(&g_red[OFF_O2 + r * 64 + 32 + t], ssq[t]);
    }
}

__global__ void kstage3(const float* __restrict__ w_o3, const float* __restrict__ b_o3,
                        float* __restrict__ out) {
    __shared__ float sv[2][32];
    int t = threadIdx.x;
    int n2 = blockIdx.x * 2;
    if (t < 64) {
        int q = t >> 5, k = t & 31;
        float a = g_y2[(n2 + q) * 32 + k] * g_coef[768 + k] + g_coef[832 + k];
        sv[q][k] = sp(a);
    }
    __syncthreads();
    int q = t >> 7, c = t & 127;
    int n = n2 + q;
    float acc = b_o3[c];
#pragma unroll
    for (int j4 = 0; j4 < 8; j4++) {
        float4 w4 = __ldg((const float4*)&w_o3[c * 32 + j4 * 4]);
        float4 v = *(const float4*)&sv[q][j4 * 4];
        acc += v.x * w4.x + v.y * w4.y + v.z * w4.z + v.w * w4.w;
    }
    if (c < 64) out[(long)n * 64 + c] = acc;
    else        out[(long)NN * 64 + (long)n * 64 + (c - 64)] = acc;
}

// ---------------- launch ----------------
extern "C" void kernel_launch(void* const* d_in, const int* in_sizes, int n_in,
                              void* d_out, int out_size) {
    const float* x         = (const float*)d_in[0];
    const int*   node_type = (const int*)d_in[1];
    const int*   edge_type = (const int*)d_in[2];
    const int*   edge_index= (const int*)d_in[3];
    const int*   batch     = (const int*)d_in[4];
    const float* node_emb  = (const float*)d_in[5];
    const float* edge_emb  = (const float*)d_in[6];
    const float* w_d1      = (const float*)d_in[7];
    const float* g_d1      = (const float*)d_in[9];
    const float* be_d1     = (const float*)d_in[10];
    const float* w_d2      = (const float*)d_in[11];
    const float* g_d2      = (const float*)d_in[13];
    const float* be_d2     = (const float*)d_in[14];
    const float* g_c1      = (const float*)d_in[15];
    const float* be_c1     = (const float*)d_in[16];
    const float* g_c2      = (const float*)d_in[17];
    const float* be_c2     = (const float*)d_in[18];
    const float* g_c3      = (const float*)d_in[19];
    const float* be_c3     = (const float*)d_in[20];
    const float* w_o1      = (const float*)d_in[21];
    const float* b_o1      = (const float*)d_in[22];
    const float* g_o1      = (const float*)d_in[23];
    const float* be_o1     = (const float*)d_in[24];
    const float* w_o2      = (const float*)d_in[25];
    const float* b_o2      = (const float*)d_in[26];
    const float* g_o2      = (const float*)d_in[27];
    const float* be_o2     = (const float*)d_in[28];
    const float* w_o3      = (const float*)d_in[29];
    const float* b_o3      = (const float*)d_in[30];

    kzero<<<196, 256>>>();
    kcount<<<(EE + 255) / 256, 256>>>(edge_index);
    kscan1<<<196, 256>>>();
    khist<<<296, 256>>>(x);
    kscan2<<<1, 256>>>();
    kscan3<<<196, 256>>>();
    kfin_d1<<<1, 64>>>(w_d1, g_d1, be_d1);
    ktable<<<NB + 1, 64>>>(w_d2);
    kd2stat<<<16, 64>>>();
    kfinbn<<<1, 64>>>(OFF_D2, 64, (float)EE, g_d2, be_d2, 128);
    ktaffine<<<((NB + 1) * 64 + 255) / 256, 256>>>();
    kscatter<<<(EE + 255) / 256, 256>>>(edge_index, edge_type, x);
    kinith<<<12500, 256>>>(node_type, node_emb);

    const int   statoff[3] = {OFF_C1, OFF_C2, OFF_C3};
    const int   coefoff[3] = {256, 384, 512};
    const float* gs[3]  = {g_c1, g_c2, g_c3};
    const float* bes[3] = {be_c1, be_c2, be_c3};
    for (int l = 0; l < 3; l++) {
        kedge<<<(EE * 8 + 255) / 256, 256>>>(edge_emb);
        knstat<<<256, 256>>>(statoff[l]);
        kfinbn<<<1, 64>>>(statoff[l], 64, (float)NN, gs[l], bes[l], coefoff[l]);
        kapply<<<3125, 256>>>(coefoff[l], (l < 2) ? 1 : 0, (l == 2) ? 1 : 0, batch);
    }

    kstage1<<<12500, 256>>>(batch, w_o1, b_o1);
    kfinbn<<<1, 64>>>(OFF_O1, 64, (float)NN, g_o1, be_o1, 640);
    kstage2<<<12500, 128>>>(w_o2, b_o2);
    kfinbn<<<1, 64>>>(OFF_O2, 32, (float)NN, g_o2, be_o2, 768);
    kstage3<<<25000, 256>>>(w_o3, b_o3, (float*)d_out);
}

// round 6
// speedup vs baseline: 1.8013x; 1.1862x over previous
#include <cuda_runtime.h>

#define NN 50000
#define EE 1250000
#define HALF 625000
#define HH 64
#define BB 500
#define BN_EPS 1e-5f

#define NB2 32768
#define XLO (-8.0f)
#define INVH2 2048.0f          // NB2/16
#define H2 4.8828125e-4f       // 16/NB2

// ---------------- device scratch ----------------
__device__ float g_T[(long)NB2 * HH];    // 8MB table; BN2 affine folded in later
__device__ int4  g_rec[EE];              // src, dst, ty|bin<<7, 0
__device__ int   g_cnt[NB2];
__device__ float g_h[NN * HH];
__device__ float g_agg[NN * HH];
__device__ float g_hg[BB * HH];
__device__ float g_y1[NN * 64];
__device__ float g_y2[NN * 32];
__device__ float g_red[22592];
__device__ float g_coef[1024];

#define OFF_X   0
#define OFF_D2  64
#define OFF_C1  4160
#define OFF_C2  8256
#define OFF_C3  12352
#define OFF_O1  16448
#define OFF_O2  20544

__device__ __forceinline__ float sp(float x) {
    float t, l;
    asm("ex2.approx.ftz.f32 %0, %1;" : "=f"(t) : "f"(x * 1.44269504f));
    asm("lg2.approx.f32 %0, %1;" : "=f"(l) : "f"(1.0f + t));
    float r = l * 0.69314718f;
    return x > 20.0f ? x : r;
}

// ---------------- setup kernels ----------------

__global__ void kzero() {
    int i = blockIdx.x * 256 + threadIdx.x;
    if (i < 22592) g_red[i] = 0.0f;
    if (i < BB * HH) g_hg[i] = 0.0f;
    if (i < NB2) g_cnt[i] = 0;
}

// one pass over edges: pack record, count bin, x stats
__global__ void kprep(const int* __restrict__ ei, const int* __restrict__ et,
                      const float* __restrict__ x) {
    int e = blockIdx.x * 256 + threadIdx.x;
    float sx = 0.f, sxx = 0.f;
    if (e < EE) {
        float xv = x[e];
        sx = xv; sxx = xv * xv;
        float u = (xv - XLO) * INVH2;
        int b = (int)u;
        b = max(0, min(NB2 - 1, b));
        atomicAdd(&g_cnt[b], 1);
        g_rec[e] = make_int4(ei[e], ei[EE + e], et[e] | (b << 7), 0);
    }
    __shared__ float ss[256], sq[256];
    int t = threadIdx.x;
    ss[t] = sx; sq[t] = sxx;
    __syncthreads();
    for (int o = 128; o > 0; o >>= 1) {
        if (t < o) { ss[t] += ss[t + o]; sq[t] += sq[t + o]; }
        __syncthreads();
    }
    if (t == 0) {
        int r = blockIdx.x & 31;
        atomicAdd(&g_red[OFF_X + 2 * r], ss[0]);
        atomicAdd(&g_red[OFF_X + 2 * r + 1], sq[0]);
    }
}

__global__ void kfin_d1(const float* __restrict__ w_d1, const float* __restrict__ g_d1,
                        const float* __restrict__ be_d1) {
    __shared__ float S[2];
    if (threadIdx.x == 0) {
        float s = 0.f, q = 0.f;
        for (int r = 0; r < 32; r++) { s += g_red[2 * r]; q += g_red[2 * r + 1]; }
        S[0] = s; S[1] = q;
    }
    __syncthreads();
    float mx = S[0] / (float)EE;
    float vx = S[1] / (float)EE - mx * mx;
    int h = threadIdx.x;
    float w = w_d1[h];
    float a = w * rsqrtf(vx * w * w + BN_EPS) * g_d1[h];
    g_coef[h] = a;
    g_coef[64 + h] = -mx * a + be_d1[h];
}

// table build: tiled GEMM, block = 64 bins x 64 k
__global__ void ktable(const float* __restrict__ w_d2) {
    __shared__ float w2s[64 * 68];   // padded rows (68 floats) to avoid bank conflicts
    __shared__ float spv[64 * 64];   // [j][f]
    int t = threadIdx.x;
    int j0 = blockIdx.x * 64;

    for (int i = t * 4; i < 4096; i += 1024) {
        float4 v = __ldg((const float4*)&w_d2[i]);
        int k = i >> 6, f = i & 63;
        *(float4*)&w2s[k * 68 + f] = v;
    }
    {
        int f = t & 63;
        float a = g_coef[f], c = g_coef[64 + f];
        for (int j = t >> 6; j < 64; j += 4) {
            float xj = XLO + ((float)(j0 + j) + 0.5f) * H2;
            spv[j * 64 + f] = sp(a * xj + c);
        }
    }
    __syncthreads();

    int k = t & 63;
    int jg = (t >> 6) * 16;
    float acc[16];
#pragma unroll
    for (int i = 0; i < 16; i++) acc[i] = 0.f;
    for (int f4 = 0; f4 < 64; f4 += 4) {
        float4 w4 = *(const float4*)&w2s[k * 68 + f4];
#pragma unroll
        for (int i = 0; i < 16; i++) {
            float4 d = *(const float4*)&spv[(jg + i) * 64 + f4];
            acc[i] += d.x * w4.x + d.y * w4.y + d.z * w4.z + d.w * w4.w;
        }
    }
#pragma unroll
    for (int i = 0; i < 16; i++)
        g_T[(long)(j0 + jg + i) * 64 + k] = acc[i];
}

// BN2 stats from counts (exact for nearest-neighbor quantized d2)
__global__ void kd2stat() {
    int k = threadIdx.x;
    int b0 = blockIdx.x * 64;
    float s = 0.f, q = 0.f;
    for (int j = 0; j < 64; j++) {
        float c = (float)g_cnt[b0 + j];
        float tv = g_T[(long)(b0 + j) * 64 + k];
        s += c * tv;
        q += c * tv * tv;
    }
    int r = blockIdx.x & 31;
    atomicAdd(&g_red[OFF_D2 + r * 128 + k], s);
    atomicAdd(&g_red[OFF_D2 + r * 128 + 64 + k], q);
}

__global__ void kfinbn(int redoff, int F, float cnt, const float* __restrict__ g,
                       const float* __restrict__ be, int coefoff) {
    int k = threadIdx.x;
    if (k >= F) return;
    float s = 0.f, q = 0.f;
    for (int r = 0; r < 32; r++) {
        s += g_red[redoff + r * 2 * F + k];
        q += g_red[redoff + r * 2 * F + F + k];
    }
    float m = s / cnt;
    float v = q / cnt - m * m;
    float sc = g[k] * rsqrtf(v + BN_EPS);
    g_coef[coefoff + k] = sc;
    g_coef[coefoff + 64 + k] = be[k] - m * sc;
}

// fold BN2 affine into table (in place, 8MB)
__global__ void ktaffine() {
    long i = (long)blockIdx.x * 256 + threadIdx.x;
    if (i >= (long)NB2 * 64) return;
    int k = (int)(i & 63);
    g_T[i] = g_T[i] * g_coef[128 + k] + g_coef[192 + k];
}

__global__ void kinith(const int* __restrict__ node_type, const float* __restrict__ node_emb) {
    int i = blockIdx.x * 256 + threadIdx.x;
    int n = i >> 6, k = i & 63;
    float v = node_emb[node_type[n] * 64 + k];
    g_h[i] = v;
    g_agg[i] = v;
}

// ---------------- gconv: per-edge, 16 thr/edge, 2 edges per thread ----------------
__global__ void kedge(const float* __restrict__ edge_emb) {
    int idx = blockIdx.x * 256 + threadIdx.x;
    int e = idx >> 4;
    if (e >= HALF) return;
    int f0 = (idx & 15) * 4;

    int4 ra = __ldg(&g_rec[e]);
    int4 rb = __ldg(&g_rec[e + HALF]);
    int tya = ra.z & 127, ba = ra.z >> 7;
    int tyb = rb.z & 127, bb = rb.z >> 7;

    float4 ta = __ldg((const float4*)&g_T[(long)ba * 64 + f0]);
    float4 tb = __ldg((const float4*)&g_T[(long)bb * 64 + f0]);
    float4 ema = __ldg((const float4*)&edge_emb[tya * 64 + f0]);
    float4 emb = __ldg((const float4*)&edge_emb[tyb * 64 + f0]);
    float4 ha = *(const float4*)&g_h[ra.x * 64 + f0];
    float4 hb = *(const float4*)&g_h[rb.x * 64 + f0];

    float a0 = sp(ha.x + ta.x * ema.x);
    float a1 = sp(ha.y + ta.y * ema.y);
    float a2 = sp(ha.z + ta.z * ema.z);
    float a3 = sp(ha.w + ta.w * ema.w);
    float b0 = sp(hb.x + tb.x * emb.x);
    float b1 = sp(hb.y + tb.y * emb.y);
    float b2 = sp(hb.z + tb.z * emb.z);
    float b3 = sp(hb.w + tb.w * emb.w);

    float* oa = &g_agg[ra.y * 64 + f0];
    float* ob = &g_agg[rb.y * 64 + f0];
    asm volatile("red.global.add.v4.f32 [%0], {%1, %2, %3, %4};"
                 :: "l"(oa), "f"(a0), "f"(a1), "f"(a2), "f"(a3) : "memory");
    asm volatile("red.global.add.v4.f32 [%0], {%1, %2, %3, %4};"
                 :: "l"(ob), "f"(b0), "f"(b1), "f"(b2), "f"(b3) : "memory");
}

__global__ void knstat(int redoff) {
    int t = threadIdx.x;
    int f0 = (t & 15) * 4;
    float4 s = {0, 0, 0, 0}, q = {0, 0, 0, 0};
    for (int n = blockIdx.x * 16 + (t >> 4); n < NN; n += gridDim.x * 16) {
        float4 v = *(const float4*)&g_agg[n * 64 + f0];
        s.x += v.x; s.y += v.y; s.z += v.z; s.w += v.w;
        q.x += v.x * v.x; q.y += v.y * v.y; q.z += v.z * v.z; q.w += v.w * v.w;
    }
    __shared__ float ssum[64], ssq[64];
    if (t < 64) { ssum[t] = 0.f; ssq[t] = 0.f; }
    __syncthreads();
    atomicAdd(&ssum[f0 + 0], s.x); atomicAdd(&ssum[f0 + 1], s.y);
    atomicAdd(&ssum[f0 + 2], s.z); atomicAdd(&ssum[f0 + 3], s.w);
    atomicAdd(&ssq[f0 + 0], q.x); atomicAdd(&ssq[f0 + 1], q.y);
    atomicAdd(&ssq[f0 + 2], q.z); atomicAdd(&ssq[f0 + 3], q.w);
    __syncthreads();
    if (t < 64) {
        int r = blockIdx.x & 31;
        atomicAdd(&g_red[redoff + r * 128 + t], ssum[t]);
        atomicAdd(&g_red[redoff + r * 128 + 64 + t], ssq[t]);
    }
}

__global__ void kapply(int coefoff, int doact, int dohg, const int* __restrict__ batch) {
    int i = blockIdx.x * 256 + threadIdx.x;
    int n = i >> 4;
    int f0 = (i & 15) * 4;
    float4 v  = *(const float4*)&g_agg[n * 64 + f0];
    float4 sc = *(const float4*)&g_coef[coefoff + f0];
    float4 sh = *(const float4*)&g_coef[coefoff + 64 + f0];
    v.x = v.x * sc.x + sh.x; v.y = v.y * sc.y + sh.y;
    v.z = v.z * sc.z + sh.z; v.w = v.w * sc.w + sh.w;
    if (doact) { v.x = sp(v.x); v.y = sp(v.y); v.z = sp(v.z); v.w = sp(v.w); }
    *(float4*)&g_h[n * 64 + f0] = v;
    *(float4*)&g_agg[n * 64 + f0] = v;   // re-init accumulator for next layer
    if (dohg) {
        int b = batch[n];
        float* o = &g_hg[b * 64 + f0];
        asm volatile("red.global.add.v4.f32 [%0], {%1, %2, %3, %4};"
                     :: "l"(o), "f"(v.x), "f"(v.y), "f"(v.z), "f"(v.w) : "memory");
    }
}

__global__ void kstage1(const int* __restrict__ batch, const float* __restrict__ w_o1,
                        const float* __restrict__ b_o1) {
    __shared__ float snf[4][128];
    __shared__ float ssum[64], ssq[64];
    int t = threadIdx.x, q = t >> 6, k = t & 63;
    int n = blockIdx.x * 4 + q;
    snf[q][k]      = g_h[n * 64 + k];
    snf[q][64 + k] = g_hg[batch[n] * 64 + k];
    if (t < 64) { ssum[t] = 0.f; ssq[t] = 0.f; }
    __syncthreads();
    float acc = b_o1[k];
#pragma unroll
    for (int j4 = 0; j4 < 32; j4++) {
        float4 w4 = __ldg((const float4*)&w_o1[k * 128 + j4 * 4]);
        float4 v = *(const float4*)&snf[q][j4 * 4];
        acc += v.x * w4.x + v.y * w4.y + v.z * w4.z + v.w * w4.w;
    }
    g_y1[n * 64 + k] = acc;
    atomicAdd(&ssum[k], acc);
    atomicAdd(&ssq[k], acc * acc);
    __syncthreads();
    if (t < 64) {
        int r = blockIdx.x & 31;
        atomicAdd(&g_red[OFF_O1 + r * 128 + t], ssum[t]);
        atomicAdd(&g_red[OFF_O1 + r * 128 + 64 + t], ssq[t]);
    }
}

__global__ void kstage2(const float* __restrict__ w_o2, const float* __restrict__ b_o2) {
    __shared__ float sv[4][64];
    __shared__ float ssum[32], ssq[32];
    int t = threadIdx.x, q = t >> 5, k = t & 31;
    int n = blockIdx.x * 4 + q;
    {
        float a = g_y1[n * 64 + k]      * g_coef[640 + k]      + g_coef[704 + k];
        float b = g_y1[n * 64 + 32 + k] * g_coef[640 + 32 + k] + g_coef[704 + 32 + k];
        sv[q][k] = sp(a);
        sv[q][32 + k] = sp(b);
    }
    if (t < 32) { ssum[t] = 0.f; ssq[t] = 0.f; }
    __syncthreads();
    float acc = b_o2[k];
#pragma unroll
    for (int j4 = 0; j4 < 16; j4++) {
        float4 w4 = __ldg((const float4*)&w_o2[k * 64 + j4 * 4]);
        float4 v = *(const float4*)&sv[q][j4 * 4];
        acc += v.x * w4.x + v.y * w4.y + v.z * w4.z + v.w * w4.w;
    }
    g_y2[n * 32 + k] = acc;
    atomicAdd(&ssum[k], acc);
    atomicAdd(&ssq[k], acc * acc);
    __syncthreads();
    if (t < 32) {
        int r = blockIdx.x & 31;
        atomicAdd(&g_red[OFF_O2 + r * 64 + t], ssum[t]);
        atomicAdd(&g_red[OFF_O2 + r * 64 + 32 + t], ssq[t]);
    }
}

__global__ void kstage3(const float* __restrict__ w_o3, const float* __restrict__ b_o3,
                        float* __restrict__ out) {
    __shared__ float sv[2][32];
    int t = threadIdx.x;
    int n2 = blockIdx.x * 2;
    if (t < 64) {
        int q = t >> 5, k = t & 31;
        float a = g_y2[(n2 + q) * 32 + k] * g_coef[768 + k] + g_coef[832 + k];
        sv[q][k] = sp(a);
    }
    __syncthreads();
    int q = t >> 7, c = t & 127;
    int n = n2 + q;
    float acc = b_o3[c];
#pragma unroll
    for (int j4 = 0; j4 < 8; j4++) {
        float4 w4 = __ldg((const float4*)&w_o3[c * 32 + j4 * 4]);
        float4 v = *(const float4*)&sv[q][j4 * 4];
        acc += v.x * w4.x + v.y * w4.y + v.z * w4.z + v.w * w4.w;
    }
    if (c < 64) out[(long)n * 64 + c] = acc;
    else        out[(long)NN * 64 + (long)n * 64 + (c - 64)] = acc;
}

// ---------------- launch ----------------
extern "C" void kernel_launch(void* const* d_in, const int* in_sizes, int n_in,
                              void* d_out, int out_size) {
    const float* x         = (const float*)d_in[0];
    const int*   node_type = (const int*)d_in[1];
    const int*   edge_type = (const int*)d_in[2];
    const int*   edge_index= (const int*)d_in[3];
    const int*   batch     = (const int*)d_in[4];
    const float* node_emb  = (const float*)d_in[5];
    const float* edge_emb  = (const float*)d_in[6];
    const float* w_d1      = (const float*)d_in[7];
    const float* g_d1      = (const float*)d_in[9];
    const float* be_d1     = (const float*)d_in[10];
    const float* w_d2      = (const float*)d_in[11];
    const float* g_d2      = (const float*)d_in[13];
    const float* be_d2     = (const float*)d_in[14];
    const float* g_c1      = (const float*)d_in[15];
    const float* be_c1     = (const float*)d_in[16];
    const float* g_c2      = (const float*)d_in[17];
    const float* be_c2     = (const float*)d_in[18];
    const float* g_c3      = (const float*)d_in[19];
    const float* be_c3     = (const float*)d_in[20];
    const float* w_o1      = (const float*)d_in[21];
    const float* b_o1      = (const float*)d_in[22];
    const float* g_o1      = (const float*)d_in[23];
    const float* be_o1     = (const float*)d_in[24];
    const float* w_o2      = (const float*)d_in[25];
    const float* b_o2      = (const float*)d_in[26];
    const float* g_o2      = (const float*)d_in[27];
    const float* be_o2     = (const float*)d_in[28];
    const float* w_o3      = (const float*)d_in[29];
    const float* b_o3      = (const float*)d_in[30];

    kzero<<<128, 256>>>();
    kprep<<<(EE + 255) / 256, 256>>>(edge_index, edge_type, x);
    kfin_d1<<<1, 64>>>(w_d1, g_d1, be_d1);
    ktable<<<NB2 / 64, 256>>>(w_d2);
    kd2stat<<<NB2 / 64, 64>>>();
    kfinbn<<<1, 64>>>(OFF_D2, 64, (float)EE, g_d2, be_d2, 128);
    ktaffine<<<(int)(((long)NB2 * 64 + 255) / 256), 256>>>();
    kinith<<<12500, 256>>>(node_type, node_emb);

    const int   statoff[3] = {OFF_C1, OFF_C2, OFF_C3};
    const int   coefoff[3] = {256, 384, 512};
    const float* gs[3]  = {g_c1, g_c2, g_c3};
    const float* bes[3] = {be_c1, be_c2, be_c3};
    for (int l = 0; l < 3; l++) {
        kedge<<<(HALF * 16 + 255) / 256, 256>>>(edge_emb);
        knstat<<<256, 256>>>(statoff[l]);
        kfinbn<<<1, 64>>>(statoff[l], 64, (float)NN, gs[l], bes[l], coefoff[l]);
        kapply<<<3125, 256>>>(coefoff[l], (l < 2) ? 1 : 0, (l == 2) ? 1 : 0, batch);
    }

    kstage1<<<12500, 256>>>(batch, w_o1, b_o1);
    kfinbn<<<1, 64>>>(OFF_O1, 64, (float)NN, g_o1, be_o1, 640);
    kstage2<<<12500, 128>>>(w_o2, b_o2);
    kfinbn<<<1, 64>>>(OFF_O2, 32, (float)NN, g_o2, be_o2, 768);
    kstage3<<<25000, 256>>>(w_o3, b_o3, (float*)d_out);
}

// round 7
// speedup vs baseline: 1.8317x; 1.0168x over previous
#include <cuda_runtime.h>
#include <cuda_fp16.h>

#define NN 50000
#define EE 1250000
#define HALF 625000
#define HH 64
#define BB 500
#define BN_EPS 1e-5f

#define NB2 32768
#define XLO (-8.0f)
#define INVH2 2048.0f          // NB2/16
#define H2 4.8828125e-4f       // 16/NB2

// ---------------- device scratch ----------------
__device__ float   g_T[(long)NB2 * HH];    // 8MB fp32 table (pre-affine, for stats)
__device__ __half2 g_Th[(long)NB2 * 32];   // 4MB fp16 table, BN2 affine folded
__device__ __half2 g_emh[100 * 32];        // fp16 edge_emb
__device__ int2    g_rec[EE];              // src|dst<<16, ty|bin<<7
__device__ int     g_cnt[NB2];
__device__ float   g_h[NN * HH];
__device__ float   g_agg[NN * HH];
__device__ float   g_hg[BB * HH];
__device__ float   g_y1[NN * 64];
__device__ float   g_y2[NN * 32];
__device__ float   g_red[22592];
__device__ float   g_coef[1024];

#define OFF_X   0
#define OFF_D2  64
#define OFF_C1  4160
#define OFF_C2  8256
#define OFF_C3  12352
#define OFF_O1  16448
#define OFF_O2  20544

__device__ __forceinline__ float sp(float x) {
    float t, l;
    asm("ex2.approx.ftz.f32 %0, %1;" : "=f"(t) : "f"(x * 1.44269504f));
    asm("lg2.approx.f32 %0, %1;" : "=f"(l) : "f"(1.0f + t));
    float r = l * 0.69314718f;
    return x > 20.0f ? x : r;
}

// ---------------- setup kernels ----------------

__global__ void kzero() {
    int i = blockIdx.x * 256 + threadIdx.x;
    if (i < 22592) g_red[i] = 0.0f;
    if (i < BB * HH) g_hg[i] = 0.0f;
    if (i < NB2) g_cnt[i] = 0;
}

// one pass over edges: pack record, count bin, x stats
__global__ void kprep(const int* __restrict__ ei, const int* __restrict__ et,
                      const float* __restrict__ x) {
    int e = blockIdx.x * 256 + threadIdx.x;
    float sx = 0.f, sxx = 0.f;
    if (e < EE) {
        float xv = x[e];
        sx = xv; sxx = xv * xv;
        float u = (xv - XLO) * INVH2;
        int b = (int)u;
        b = max(0, min(NB2 - 1, b));
        atomicAdd(&g_cnt[b], 1);
        g_rec[e] = make_int2(ei[e] | (ei[EE + e] << 16), et[e] | (b << 7));
    }
    __shared__ float ss[256], sq[256];
    int t = threadIdx.x;
    ss[t] = sx; sq[t] = sxx;
    __syncthreads();
    for (int o = 128; o > 0; o >>= 1) {
        if (t < o) { ss[t] += ss[t + o]; sq[t] += sq[t + o]; }
        __syncthreads();
    }
    if (t == 0) {
        int r = blockIdx.x & 31;
        atomicAdd(&g_red[OFF_X + 2 * r], ss[0]);
        atomicAdd(&g_red[OFF_X + 2 * r + 1], sq[0]);
    }
}

__global__ void kfin_d1(const float* __restrict__ w_d1, const float* __restrict__ g_d1,
                        const float* __restrict__ be_d1) {
    __shared__ float S[2];
    if (threadIdx.x == 0) {
        float s = 0.f, q = 0.f;
        for (int r = 0; r < 32; r++) { s += g_red[2 * r]; q += g_red[2 * r + 1]; }
        S[0] = s; S[1] = q;
    }
    __syncthreads();
    float mx = S[0] / (float)EE;
    float vx = S[1] / (float)EE - mx * mx;
    int h = threadIdx.x;
    float w = w_d1[h];
    float a = w * rsqrtf(vx * w * w + BN_EPS) * g_d1[h];
    g_coef[h] = a;
    g_coef[64 + h] = -mx * a + be_d1[h];
}

// table build: tiled GEMM, block = 64 bins x 64 k
__global__ void ktable(const float* __restrict__ w_d2) {
    __shared__ float w2s[64 * 68];
    __shared__ float spv[64 * 64];
    int t = threadIdx.x;
    int j0 = blockIdx.x * 64;

    for (int i = t * 4; i < 4096; i += 1024) {
        float4 v = __ldg((const float4*)&w_d2[i]);
        int k = i >> 6, f = i & 63;
        *(float4*)&w2s[k * 68 + f] = v;
    }
    {
        int f = t & 63;
        float a = g_coef[f], c = g_coef[64 + f];
        for (int j = t >> 6; j < 64; j += 4) {
            float xj = XLO + ((float)(j0 + j) + 0.5f) * H2;
            spv[j * 64 + f] = sp(a * xj + c);
        }
    }
    __syncthreads();

    int k = t & 63;
    int jg = (t >> 6) * 16;
    float acc[16];
#pragma unroll
    for (int i = 0; i < 16; i++) acc[i] = 0.f;
    for (int f4 = 0; f4 < 64; f4 += 4) {
        float4 w4 = *(const float4*)&w2s[k * 68 + f4];
#pragma unroll
        for (int i = 0; i < 16; i++) {
            float4 d = *(const float4*)&spv[(jg + i) * 64 + f4];
            acc[i] += d.x * w4.x + d.y * w4.y + d.z * w4.z + d.w * w4.w;
        }
    }
#pragma unroll
    for (int i = 0; i < 16; i++)
        g_T[(long)(j0 + jg + i) * 64 + k] = acc[i];
}

// BN2 stats from counts (exact for nearest-neighbor quantized d2)
__global__ void kd2stat() {
    int k = threadIdx.x;
    int b0 = blockIdx.x * 64;
    float s = 0.f, q = 0.f;
    for (int j = 0; j < 64; j++) {
        float c = (float)g_cnt[b0 + j];
        float tv = g_T[(long)(b0 + j) * 64 + k];
        s += c * tv;
        q += c * tv * tv;
    }
    int r = blockIdx.x & 31;
    atomicAdd(&g_red[OFF_D2 + r * 128 + k], s);
    atomicAdd(&g_red[OFF_D2 + r * 128 + 64 + k], q);
}

__global__ void kfinbn(int redoff, int F, float cnt, const float* __restrict__ g,
                       const float* __restrict__ be, int coefoff) {
    int k = threadIdx.x;
    if (k >= F) return;
    float s = 0.f, q = 0.f;
    for (int r = 0; r < 32; r++) {
        s += g_red[redoff + r * 2 * F + k];
        q += g_red[redoff + r * 2 * F + F + k];
    }
    float m = s / cnt;
    float v = q / cnt - m * m;
    float sc = g[k] * rsqrtf(v + BN_EPS);
    g_coef[coefoff + k] = sc;
    g_coef[coefoff + 64 + k] = be[k] - m * sc;
}

// fold BN2 affine into fp16 table
__global__ void ktaffine() {
    long i = (long)blockIdx.x * 256 + threadIdx.x;
    if (i >= (long)NB2 * 32) return;
    long b = i >> 5;
    int k2 = (int)(i & 31) * 2;
    float v0 = g_T[b * 64 + k2]     * g_coef[128 + k2]     + g_coef[192 + k2];
    float v1 = g_T[b * 64 + k2 + 1] * g_coef[128 + k2 + 1] + g_coef[192 + k2 + 1];
    g_Th[i] = __floats2half2_rn(v0, v1);
}

__global__ void kemh(const float* __restrict__ edge_emb) {
    int i = blockIdx.x * 256 + threadIdx.x;
    if (i >= 100 * 32) return;
    g_emh[i] = __floats2half2_rn(edge_emb[2 * i], edge_emb[2 * i + 1]);
}

__global__ void kinith(const int* __restrict__ node_type, const float* __restrict__ node_emb) {
    int i = blockIdx.x * 256 + threadIdx.x;
    int n = i >> 6, k = i & 63;
    float v = node_emb[node_type[n] * 64 + k];
    g_h[i] = v;
    g_agg[i] = v;
}

// ---------------- gconv: per-edge, 16 thr/edge, 2 edges/thread, fp16 T/em ----------------
__global__ void kedge() {
    int idx = blockIdx.x * 256 + threadIdx.x;
    int e = idx >> 4;
    if (e >= HALF) return;
    int l = idx & 15;
    int f0 = l * 4;

    int2 ra = __ldg(&g_rec[e]);
    int2 rb = __ldg(&g_rec[e + HALF]);
    unsigned wa = (unsigned)ra.x, wb = (unsigned)rb.x;
    int sa = wa & 0xffffu, da = wa >> 16;
    int sb = wb & 0xffffu, db = wb >> 16;
    int tya = ra.y & 127; long ba = ra.y >> 7;
    int tyb = rb.y & 127; long bb = rb.y >> 7;

    uint2 tra = __ldg((const uint2*)&g_Th[ba * 32 + l * 2]);
    uint2 trb = __ldg((const uint2*)&g_Th[bb * 32 + l * 2]);
    uint2 era = __ldg((const uint2*)&g_emh[tya * 32 + l * 2]);
    uint2 erb = __ldg((const uint2*)&g_emh[tyb * 32 + l * 2]);
    float4 ha = *(const float4*)&g_h[sa * 64 + f0];
    float4 hb = *(const float4*)&g_h[sb * 64 + f0];

    float2 ta0 = __half22float2(*(const __half2*)&tra.x);
    float2 ta1 = __half22float2(*(const __half2*)&tra.y);
    float2 ea0 = __half22float2(*(const __half2*)&era.x);
    float2 ea1 = __half22float2(*(const __half2*)&era.y);
    float2 tb0 = __half22float2(*(const __half2*)&trb.x);
    float2 tb1 = __half22float2(*(const __half2*)&trb.y);
    float2 eb0 = __half22float2(*(const __half2*)&erb.x);
    float2 eb1 = __half22float2(*(const __half2*)&erb.y);

    float a0 = sp(ha.x + ta0.x * ea0.x);
    float a1 = sp(ha.y + ta0.y * ea0.y);
    float a2 = sp(ha.z + ta1.x * ea1.x);
    float a3 = sp(ha.w + ta1.y * ea1.y);
    float b0 = sp(hb.x + tb0.x * eb0.x);
    float b1 = sp(hb.y + tb0.y * eb0.y);
    float b2 = sp(hb.z + tb1.x * eb1.x);
    float b3 = sp(hb.w + tb1.y * eb1.y);

    float* oa = &g_agg[da * 64 + f0];
    float* ob = &g_agg[db * 64 + f0];
    asm volatile("red.global.add.v4.f32 [%0], {%1, %2, %3, %4};"
                 :: "l"(oa), "f"(a0), "f"(a1), "f"(a2), "f"(a3) : "memory");
    asm volatile("red.global.add.v4.f32 [%0], {%1, %2, %3, %4};"
                 :: "l"(ob), "f"(b0), "f"(b1), "f"(b2), "f"(b3) : "memory");
}

__global__ void knstat(int redoff) {
    int t = threadIdx.x;
    int f0 = (t & 15) * 4;
    float4 s = {0, 0, 0, 0}, q = {0, 0, 0, 0};
    for (int n = blockIdx.x * 16 + (t >> 4); n < NN; n += gridDim.x * 16) {
        float4 v = *(const float4*)&g_agg[n * 64 + f0];
        s.x += v.x; s.y += v.y; s.z += v.z; s.w += v.w;
        q.x += v.x * v.x; q.y += v.y * v.y; q.z += v.z * v.z; q.w += v.w * v.w;
    }
    __shared__ float ssum[64], ssq[64];
    if (t < 64) { ssum[t] = 0.f; ssq[t] = 0.f; }
    __syncthreads();
    atomicAdd(&ssum[f0 + 0], s.x); atomicAdd(&ssum[f0 + 1], s.y);
    atomicAdd(&ssum[f0 + 2], s.z); atomicAdd(&ssum[f0 + 3], s.w);
    atomicAdd(&ssq[f0 + 0], q.x); atomicAdd(&ssq[f0 + 1], q.y);
    atomicAdd(&ssq[f0 + 2], q.z); atomicAdd(&ssq[f0 + 3], q.w);
    __syncthreads();
    if (t < 64) {
        int r = blockIdx.x & 31;
        atomicAdd(&g_red[redoff + r * 128 + t], ssum[t]);
        atomicAdd(&g_red[redoff + r * 128 + 64 + t], ssq[t]);
    }
}

__global__ void kapply(int coefoff, int doact, int dohg, const int* __restrict__ batch) {
    int i = blockIdx.x * 256 + threadIdx.x;
    int n = i >> 4;
    int f0 = (i & 15) * 4;
    float4 v  = *(const float4*)&g_agg[n * 64 + f0];
    float4 sc = *(const float4*)&g_coef[coefoff + f0];
    float4 sh = *(const float4*)&g_coef[coefoff + 64 + f0];
    v.x = v.x * sc.x + sh.x; v.y = v.y * sc.y + sh.y;
    v.z = v.z * sc.z + sh.z; v.w = v.w * sc.w + sh.w;
    if (doact) { v.x = sp(v.x); v.y = sp(v.y); v.z = sp(v.z); v.w = sp(v.w); }
    *(float4*)&g_h[n * 64 + f0] = v;
    *(float4*)&g_agg[n * 64 + f0] = v;   // re-init accumulator for next layer
    if (dohg) {
        int b = batch[n];
        float* o = &g_hg[b * 64 + f0];
        asm volatile("red.global.add.v4.f32 [%0], {%1, %2, %3, %4};"
                     :: "l"(o), "f"(v.x), "f"(v.y), "f"(v.z), "f"(v.w) : "memory");
    }
}

__global__ void kstage1(const int* __restrict__ batch, const float* __restrict__ w_o1,
                        const float* __restrict__ b_o1) {
    __shared__ float snf[4][128];
    __shared__ float ssum[64], ssq[64];
    int t = threadIdx.x, q = t >> 6, k = t & 63;
    int n = blockIdx.x * 4 + q;
    snf[q][k]      = g_h[n * 64 + k];
    snf[q][64 + k] = g_hg[batch[n] * 64 + k];
    if (t < 64) { ssum[t] = 0.f; ssq[t] = 0.f; }
    __syncthreads();
    float acc = b_o1[k];
#pragma unroll
    for (int j4 = 0; j4 < 32; j4++) {
        float4 w4 = __ldg((const float4*)&w_o1[k * 128 + j4 * 4]);
        float4 v = *(const float4*)&snf[q][j4 * 4];
        acc += v.x * w4.x + v.y * w4.y + v.z * w4.z + v.w * w4.w;
    }
    g_y1[n * 64 + k] = acc;
    atomicAdd(&ssum[k], acc);
    atomicAdd(&ssq[k], acc * acc);
    __syncthreads();
    if (t < 64) {
        int r = blockIdx.x & 31;
        atomicAdd(&g_red[OFF_O1 + r * 128 + t], ssum[t]);
        atomicAdd(&g_red[OFF_O1 + r * 128 + 64 + t], ssq[t]);
    }
}

__global__ void kstage2(const float* __restrict__ w_o2, const float* __restrict__ b_o2) {
    __shared__ float sv[4][64];
    __shared__ float ssum[32], ssq[32];
    int t = threadIdx.x, q = t >> 5, k = t & 31;
    int n = blockIdx.x * 4 + q;
    {
        float a = g_y1[n * 64 + k]      * g_coef[640 + k]      + g_coef[704 + k];
        float b = g_y1[n * 64 + 32 + k] * g_coef[640 + 32 + k] + g_coef[704 + 32 + k];
        sv[q][k] = sp(a);
        sv[q][32 + k] = sp(b);
    }
    if (t < 32) { ssum[t] = 0.f; ssq[t] = 0.f; }
    __syncthreads();
    float acc = b_o2[k];
#pragma unroll
    for (int j4 = 0; j4 < 16; j4++) {
        float4 w4 = __ldg((const float4*)&w_o2[k * 64 + j4 * 4]);
        float4 v = *(const float4*)&sv[q][j4 * 4];
        acc += v.x * w4.x + v.y * w4.y + v.z * w4.z + v.w * w4.w;
    }
    g_y2[n * 32 + k] = acc;
    atomicAdd(&ssum[k], acc);
    atomicAdd(&ssq[k], acc * acc);
    __syncthreads();
    if (t < 32) {
        int r = blockIdx.x & 31;
        atomicAdd(&g_red[OFF_O2 + r * 64 + t], ssum[t]);
        atomicAdd(&g_red[OFF_O2 + r * 64 + 32 + t], ssq[t]);
    }
}

__global__ void kstage3(const float* __restrict__ w_o3, const float* __restrict__ b_o3,
                        float* __restrict__ out) {
    __shared__ float sv[2][32];
    int t = threadIdx.x;
    int n2 = blockIdx.x * 2;
    if (t < 64) {
        int q = t >> 5, k = t & 31;
        float a = g_y2[(n2 + q) * 32 + k] * g_coef[768 + k] + g_coef[832 + k];
        sv[q][k] = sp(a);
    }
    __syncthreads();
    int q = t >> 7, c = t & 127;
    int n = n2 + q;
    float acc = b_o3[c];
#pragma unroll
    for (int j4 = 0; j4 < 8; j4++) {
        float4 w4 = __ldg((const float4*)&w_o3[c * 32 + j4 * 4]);
        float4 v = *(const float4*)&sv[q][j4 * 4];
        acc += v.x * w4.x + v.y * w4.y + v.z * w4.z + v.w * w4.w;
    }
    if (c < 64) out[(long)n * 64 + c] = acc;
    else        out[(long)NN * 64 + (long)n * 64 + (c - 64)] = acc;
}

// ---------------- launch ----------------
extern "C" void kernel_launch(void* const* d_in, const int* in_sizes, int n_in,
                              void* d_out, int out_size) {
    const float* x         = (const float*)d_in[0];
    const int*   node_type = (const int*)d_in[1];
    const int*   edge_type = (const int*)d_in[2];
    const int*   edge_index= (const int*)d_in[3];
    const int*   batch     = (const int*)d_in[4];
    const float* node_emb  = (const float*)d_in[5];
    const float* edge_emb  = (const float*)d_in[6];
    const float* w_d1      = (const float*)d_in[7];
    const float* g_d1      = (const float*)d_in[9];
    const float* be_d1     = (const float*)d_in[10];
    const float* w_d2      = (const float*)d_in[11];
    const float* g_d2      = (const float*)d_in[13];
    const float* be_d2     = (const float*)d_in[14];
    const float* g_c1      = (const float*)d_in[15];
    const float* be_c1     = (const float*)d_in[16];
    const float* g_c2      = (const float*)d_in[17];
    const float* be_c2     = (const float*)d_in[18];
    const float* g_c3      = (const float*)d_in[19];
    const float* be_c3     = (const float*)d_in[20];
    const float* w_o1      = (const float*)d_in[21];
    const float* b_o1      = (const float*)d_in[22];
    const float* g_o1      = (const float*)d_in[23];
    const float* be_o1     = (const float*)d_in[24];
    const float* w_o2      = (const float*)d_in[25];
    const float* b_o2      = (const float*)d_in[26];
    const float* g_o2      = (const float*)d_in[27];
    const float* be_o2     = (const float*)d_in[28];
    const float* w_o3      = (const float*)d_in[29];
    const float* b_o3      = (const float*)d_in[30];

    kzero<<<128, 256>>>();
    kprep<<<(EE + 255) / 256, 256>>>(edge_index, edge_type, x);
    kfin_d1<<<1, 64>>>(w_d1, g_d1, be_d1);
    ktable<<<NB2 / 64, 256>>>(w_d2);
    kd2stat<<<NB2 / 64, 64>>>();
    kfinbn<<<1, 64>>>(OFF_D2, 64, (float)EE, g_d2, be_d2, 128);
    ktaffine<<<(int)(((long)NB2 * 32 + 255) / 256), 256>>>();
    kemh<<<13, 256>>>(edge_emb);
    kinith<<<12500, 256>>>(node_type, node_emb);

    const int   statoff[3] = {OFF_C1, OFF_C2, OFF_C3};
    const int   coefoff[3] = {256, 384, 512};
    const float* gs[3]  = {g_c1, g_c2, g_c3};
    const float* bes[3] = {be_c1, be_c2, be_c3};
    for (int l = 0; l < 3; l++) {
        kedge<<<(HALF * 16 + 255) / 256, 256>>>();
        knstat<<<256, 256>>>(statoff[l]);
        kfinbn<<<1, 64>>>(statoff[l], 64, (float)NN, gs[l], bes[l], coefoff[l]);
        kapply<<<3125, 256>>>(coefoff[l], (l < 2) ? 1 : 0, (l == 2) ? 1 : 0, batch);
    }

    kstage1<<<12500, 256>>>(batch, w_o1, b_o1);
    kfinbn<<<1, 64>>>(OFF_O1, 64, (float)NN, g_o1, be_o1, 640);
    kstage2<<<12500, 128>>>(w_o2, b_o2);
    kfinbn<<<1, 64>>>(OFF_O2, 32, (float)NN, g_o2, be_o2, 768);
    kstage3<<<25000, 256>>>(w_o3, b_o3, (float*)d_out);
}